// round 11
// baseline (speedup 1.0000x reference)
#include <cuda_runtime.h>
#include <cuda_bf16.h>

typedef unsigned int u32;
typedef unsigned long long u64;

#define Bc   64
#define DINc 150528
#define Dc   512
#define Cc   100
#define Mc   64
#define NFc  256
#define KC   2048
#define NCH  74          // 73 full chunks of 2048 + last chunk of 1024
#define DT   256

__device__ float g_partial[NCH * Bc * Dc];   // split-K partials [chunk][b][d]
__device__ float g_f[Bc * Dc];
__device__ float g_cnt[Cc * Dc];
__device__ float g_spart[Cc * Mc * 128];     // S[c][m][j] (j padded to 128)
__device__ float g_w[Cc * Mc];
__device__ float g_kwd[Cc * Dc];

// ---------------- helpers ----------------
__device__ __forceinline__ u32 smem_u32(const void* p) {
    u32 a;
    asm("{ .reg .u64 t; cvta.to.shared.u64 t, %1; cvt.u32.u64 %0, t; }" : "=r"(a) : "l"(p));
    return a;
}
__device__ __forceinline__ void cvt_split(float x0, float x1, u32& h, u32& l) {
    asm("cvt.rn.bf16x2.f32 %0, %1, %2;" : "=r"(h) : "f"(x1), "f"(x0));
    float h0 = __int_as_float(h << 16);
    float h1 = __int_as_float(h & 0xFFFF0000u);
    asm("cvt.rn.bf16x2.f32 %0, %1, %2;" : "=r"(l) : "f"(x1 - h1), "f"(x0 - h0));
}
__device__ __forceinline__ void ldmA(u32* r, u32 addr) {
    asm volatile("ldmatrix.sync.aligned.m8n8.x4.shared.b16 {%0,%1,%2,%3}, [%4];"
        : "=r"(r[0]), "=r"(r[1]), "=r"(r[2]), "=r"(r[3]) : "r"(addr));
}
__device__ __forceinline__ void ldmBT(u32* r, u32 addr) {
    asm volatile("ldmatrix.sync.aligned.m8n8.x4.trans.shared.b16 {%0,%1,%2,%3}, [%4];"
        : "=r"(r[0]), "=r"(r[1]), "=r"(r[2]), "=r"(r[3]) : "r"(addr));
}
__device__ __forceinline__ void mma16816(float* c, const u32* a, u32 b0, u32 b1) {
    asm volatile(
        "mma.sync.aligned.m16n8k16.row.col.f32.bf16.bf16.f32 "
        "{%0,%1,%2,%3}, {%4,%5,%6,%7}, {%8,%9}, {%0,%1,%2,%3};"
        : "+f"(c[0]), "+f"(c[1]), "+f"(c[2]), "+f"(c[3])
        : "r"(a[0]), "r"(a[1]), "r"(a[2]), "r"(a[3]), "r"(b0), "r"(b1));
}

// ---------------------------------------------------------------------------
// K1: split-bf16 3-pass HMMA split-K GEMM.  DT=256, 512 threads, KC=2048.
// grid(2, 74) = 148 CTAs = one wave.  88064 B smem.  (Measured ~90us.)
// ---------------------------------------------------------------------------
#define A_STRIDE 20
#define B_STRIDE 132
#define A_BUF (64 * A_STRIDE)
#define B_BUF (32 * B_STRIDE)
#define GEMM_SMEM ((4 * A_BUF + 4 * B_BUF) * 4)   // 88064 B

__global__ void __launch_bounds__(512, 1)
gemm_mma_kernel(const float* __restrict__ A, const float* __restrict__ W) {
    extern __shared__ u32 dsm[];
    u32* AsH = dsm;
    u32* AsL = dsm + 2 * A_BUF;
    u32* BsH = dsm + 4 * A_BUF;
    u32* BsL = dsm + 4 * A_BUF + 2 * B_BUF;

    const int t = threadIdx.x, w = t >> 5, l = t & 31;
    const int wm = w >> 3, wn = w & 7;
    const int dt0 = blockIdx.x * DT;
    const size_t kb = (size_t)blockIdx.y * KC;
    const int kmax = (kb + KC <= DINc) ? KC : (int)(DINc - kb);

    const u32 aRowOff = (u32)(wm * 32 + (l & 7) + ((l >> 3) & 1) * 8) * (A_STRIDE * 4)
                        + ((l & 16) ? 16u : 0u);
    const u32 bOff = (u32)((l & 7) + ((l >> 3) & 1) * 8) * (B_STRIDE * 4)
                     + (u32)(wn * 32 + ((l & 16) ? 8 : 0)) * 2;

    const int am = t >> 3, akq = t & 7;
    const int bk = t >> 6, bdq = t & 63;
    const float* Ap = A + (size_t)am * DINc + kb + akq * 4;
    const float* Wp = W + (size_t)(kb + bk) * Dc + dt0 + bdq * 4;

    float acc[2][4][4];
#pragma unroll
    for (int i = 0; i < 2; i++)
#pragma unroll
        for (int j = 0; j < 4; j++)
#pragma unroll
            for (int q = 0; q < 4; q++) acc[i][j][q] = 0.f;

    float4 pfA;
    float4 pfB[4];
    pfA = *(const float4*)Ap;
#pragma unroll
    for (int i = 0; i < 4; i++) pfB[i] = *(const float4*)(Wp + (size_t)(i * 8) * Dc);

    for (int k0 = 0; k0 < kmax; k0 += 32) {
        const int buf = (k0 >> 5) & 1;
        u32* aH = AsH + buf * A_BUF;
        u32* aL = AsL + buf * A_BUF;
        u32* bH = BsH + buf * B_BUF;
        u32* bL = BsL + buf * B_BUF;

        {
            u32 h0, l0, h1, l1;
            cvt_split(pfA.x, pfA.y, h0, l0);
            cvt_split(pfA.z, pfA.w, h1, l1);
            int woff = am * A_STRIDE + akq * 2;
            *(u64*)&aH[woff] = ((u64)h1 << 32) | h0;
            *(u64*)&aL[woff] = ((u64)l1 << 32) | l0;
        }
#pragma unroll
        for (int i = 0; i < 4; i++) {
            u32 h0, l0, h1, l1;
            cvt_split(pfB[i].x, pfB[i].y, h0, l0);
            cvt_split(pfB[i].z, pfB[i].w, h1, l1);
            int woff = (i * 8 + bk) * B_STRIDE + bdq * 2;
            *(u64*)&bH[woff] = ((u64)h1 << 32) | h0;
            *(u64*)&bL[woff] = ((u64)l1 << 32) | l0;
        }
        if (k0 + 32 < kmax) {
            pfA = *(const float4*)(Ap + k0 + 32);
#pragma unroll
            for (int i = 0; i < 4; i++)
                pfB[i] = *(const float4*)(Wp + (size_t)(i * 8 + k0 + 32) * Dc);
        }
        __syncthreads();

        const u32 aHb = smem_u32(aH), aLb = smem_u32(aL);
        const u32 bHb = smem_u32(bH), bLb = smem_u32(bL);
#pragma unroll
        for (int ks = 0; ks < 2; ks++) {
            u32 fAH[2][4], fAL[2][4];
            ldmA(fAH[0], aHb + aRowOff + ks * 32);
            ldmA(fAH[1], aHb + aRowOff + 16 * (A_STRIDE * 4) + ks * 32);
            ldmA(fAL[0], aLb + aRowOff + ks * 32);
            ldmA(fAL[1], aLb + aRowOff + 16 * (A_STRIDE * 4) + ks * 32);
#pragma unroll
            for (int j = 0; j < 2; j++) {
                u32 fBH[4], fBL[4];
                ldmBT(fBH, bHb + bOff + ks * 16 * (B_STRIDE * 4) + j * 32);
                ldmBT(fBL, bLb + bOff + ks * 16 * (B_STRIDE * 4) + j * 32);
#pragma unroll
                for (int mt = 0; mt < 2; mt++) {
                    mma16816(acc[mt][2 * j],     fAH[mt], fBH[0], fBH[1]);
                    mma16816(acc[mt][2 * j + 1], fAH[mt], fBH[2], fBH[3]);
                    mma16816(acc[mt][2 * j],     fAH[mt], fBL[0], fBL[1]);
                    mma16816(acc[mt][2 * j + 1], fAH[mt], fBL[2], fBL[3]);
                    mma16816(acc[mt][2 * j],     fAL[mt], fBH[0], fBH[1]);
                    mma16816(acc[mt][2 * j + 1], fAL[mt], fBH[2], fBH[3]);
                }
            }
        }
    }

    const int g = l >> 2, t4 = l & 3;
#pragma unroll
    for (int mt = 0; mt < 2; mt++)
#pragma unroll
        for (int nt = 0; nt < 4; nt++) {
            int m = wm * 32 + mt * 16 + g;
            int n = dt0 + wn * 32 + nt * 8 + t4 * 2;
            size_t o = ((size_t)(blockIdx.y * 64 + m)) * Dc + n;
            *(float2*)&g_partial[o] =
                make_float2(acc[mt][nt][0], acc[mt][nt][1]);
            *(float2*)&g_partial[o + 8 * (size_t)Dc] =
                make_float2(acc[mt][nt][2], acc[mt][nt][3]);
        }
}

// ---------------------------------------------------------------------------
// K2: fused reduce split-K + L2-normalize. grid(64), 512 threads.
// ---------------------------------------------------------------------------
__global__ void __launch_bounds__(512)
rednorm_kernel() {
    const int b = blockIdx.x;
    const int t = threadIdx.x;
    float v = 0.f;
#pragma unroll 2
    for (int ch = 0; ch < NCH; ch++)
        v += g_partial[((size_t)ch * Bc + b) * Dc + t];

    float sq = v * v;
    sq += __shfl_xor_sync(0xffffffffu, sq, 1);
    sq += __shfl_xor_sync(0xffffffffu, sq, 2);
    sq += __shfl_xor_sync(0xffffffffu, sq, 4);
    sq += __shfl_xor_sync(0xffffffffu, sq, 8);
    sq += __shfl_xor_sync(0xffffffffu, sq, 16);

    __shared__ float wsum[16];
    __shared__ float inv;
    if ((t & 31) == 0) wsum[t >> 5] = sq;
    __syncthreads();
    if (t < 32) {
        float s = (t < 16) ? wsum[t] : 0.f;
        s += __shfl_xor_sync(0xffffffffu, s, 1);
        s += __shfl_xor_sync(0xffffffffu, s, 2);
        s += __shfl_xor_sync(0xffffffffu, s, 4);
        s += __shfl_xor_sync(0xffffffffu, s, 8);
        if (t == 0) inv = rsqrtf(s);
    }
    __syncthreads();
    g_f[b * Dc + t] = v * inv;
}

// ---------------------------------------------------------------------------
// K3: index multiplicity via shared histogram (for kwd). grid(100), 256 thr.
// ---------------------------------------------------------------------------
__global__ void __launch_bounds__(256)
cnt_kernel(const int* __restrict__ indices) {
    __shared__ int h[Dc];
    const int c = blockIdx.x;
    const int t = threadIdx.x;
    h[t] = 0;
    h[t + 256] = 0;
    __syncthreads();
    atomicAdd(&h[indices[c * NFc + t]], 1);
    __syncthreads();
    g_cnt[c * Dc + t]       = (float)h[t];
    g_cnt[c * Dc + t + 256] = (float)h[t + 256];
}

// ---------------------------------------------------------------------------
// K4: skey via split-bf16 3-pass HMMA.  Per class:
//   S[m][j] = sum_k keys[c,m,k] * (cnt[c,k] * text[j,k]),  M=64, N=128(100), K=512
// grid(100), 256 threads (8 warps 2x4, warp tile 32x32).  Dyn smem 57344 B.
// B tile built transposed ([k][j]) at conversion time; cnt from in-kernel hist.
// ---------------------------------------------------------------------------
#define SA_STRIDE 20
#define SB_STRIDE 68
#define SA_BUF (64 * SA_STRIDE)     // 1280 u32
#define SB_BUF (32 * SB_STRIDE)     // 2176 u32
#define SKEY_SMEM ((4 * SA_BUF + 4 * SB_BUF + 512) * 4)   // 57344 B

__global__ void __launch_bounds__(256, 1)
skey_kernel(const float* __restrict__ keys, const float* __restrict__ text,
            const int* __restrict__ indices) {
    extern __shared__ u32 dsm[];
    u32* AsH = dsm;
    u32* AsL = dsm + 2 * SA_BUF;
    u32* BsH = dsm + 4 * SA_BUF;
    u32* BsL = dsm + 4 * SA_BUF + 2 * SB_BUF;
    int* hist = (int*)(dsm + 4 * SA_BUF + 4 * SB_BUF);

    const int c = blockIdx.x;
    const int t = threadIdx.x, w = t >> 5, l = t & 31;
    const int wm = w >> 2, wn = w & 3;

    // per-class index histogram
    hist[t] = 0;
    hist[t + 256] = 0;
    __syncthreads();
    atomicAdd(&hist[indices[c * NFc + t]], 1);
    __syncthreads();

    const u32 aRowOff = (u32)(wm * 32 + (l & 7) + ((l >> 3) & 1) * 8) * (SA_STRIDE * 4)
                        + ((l & 16) ? 16u : 0u);
    const u32 bOff = (u32)((l & 7) + ((l >> 3) & 1) * 8) * (SB_STRIDE * 4)
                     + (u32)(wn * 32 + ((l & 16) ? 8 : 0)) * 2;

    const int am = t >> 3, akq = t & 7;      // A loader (2 iters)
    const int jj = t & 63, kq0 = t >> 6;     // B loader (2 iters, kq = kq0, kq0+4)
    const int j0 = jj * 2;

    float acc[2][4][4];
#pragma unroll
    for (int i = 0; i < 2; i++)
#pragma unroll
        for (int j = 0; j < 4; j++)
#pragma unroll
            for (int q = 0; q < 4; q++) acc[i][j][q] = 0.f;

    for (int k0 = 0; k0 < Dc; k0 += 32) {
        const int buf = (k0 >> 5) & 1;
        u32* aH = AsH + buf * SA_BUF;
        u32* aL = AsL + buf * SA_BUF;
        u32* bH = BsH + buf * SB_BUF;
        u32* bL = BsL + buf * SB_BUF;

        // A: keys rows, 64 m x 32 k
#pragma unroll
        for (int i = 0; i < 2; i++) {
            int idx = i * 256 + t;
            int m = idx >> 3, kq = idx & 7;
            float4 v = *(const float4*)&keys[((size_t)(c * Mc + m)) * Dc + k0 + kq * 4];
            u32 h0, l0, h1, l1;
            cvt_split(v.x, v.y, h0, l0);
            cvt_split(v.z, v.w, h1, l1);
            int woff = m * SA_STRIDE + kq * 2;
            *(u64*)&aH[woff] = ((u64)h1 << 32) | h0;
            *(u64*)&aL[woff] = ((u64)l1 << 32) | l0;
        }
        // B: (text * cnt) transposed into [k][j] pair-packed layout
#pragma unroll
        for (int it = 0; it < 2; it++) {
            int kq = kq0 + it * 4;
            float4 t0 = make_float4(0.f, 0.f, 0.f, 0.f);
            float4 t1 = make_float4(0.f, 0.f, 0.f, 0.f);
            if (j0 < Cc)     t0 = *(const float4*)&text[(size_t)j0 * Dc + k0 + kq * 4];
            if (j0 + 1 < Cc) t1 = *(const float4*)&text[(size_t)(j0 + 1) * Dc + k0 + kq * 4];
            float cs0 = (float)hist[k0 + kq * 4 + 0];
            float cs1 = (float)hist[k0 + kq * 4 + 1];
            float cs2 = (float)hist[k0 + kq * 4 + 2];
            float cs3 = (float)hist[k0 + kq * 4 + 3];
            float a0[4] = {t0.x * cs0, t0.y * cs1, t0.z * cs2, t0.w * cs3};
            float a1[4] = {t1.x * cs0, t1.y * cs1, t1.z * cs2, t1.w * cs3};
#pragma unroll
            for (int s = 0; s < 4; s++) {
                u32 h, lo;
                cvt_split(a0[s], a1[s], h, lo);   // pair (j0, j0+1)
                int woff = (kq * 4 + s) * SB_STRIDE + jj;
                bH[woff] = h;
                bL[woff] = lo;
            }
        }
        __syncthreads();

        const u32 aHb = smem_u32(aH), aLb = smem_u32(aL);
        const u32 bHb = smem_u32(bH), bLb = smem_u32(bL);
#pragma unroll
        for (int ks = 0; ks < 2; ks++) {
            u32 fAH[2][4], fAL[2][4];
            ldmA(fAH[0], aHb + aRowOff + ks * 32);
            ldmA(fAH[1], aHb + aRowOff + 16 * (SA_STRIDE * 4) + ks * 32);
            ldmA(fAL[0], aLb + aRowOff + ks * 32);
            ldmA(fAL[1], aLb + aRowOff + 16 * (SA_STRIDE * 4) + ks * 32);
#pragma unroll
            for (int j = 0; j < 2; j++) {
                u32 fBH[4], fBL[4];
                ldmBT(fBH, bHb + bOff + ks * 16 * (SB_STRIDE * 4) + j * 32);
                ldmBT(fBL, bLb + bOff + ks * 16 * (SB_STRIDE * 4) + j * 32);
#pragma unroll
                for (int mt = 0; mt < 2; mt++) {
                    mma16816(acc[mt][2 * j],     fAH[mt], fBH[0], fBH[1]);
                    mma16816(acc[mt][2 * j + 1], fAH[mt], fBH[2], fBH[3]);
                    mma16816(acc[mt][2 * j],     fAH[mt], fBL[0], fBL[1]);
                    mma16816(acc[mt][2 * j + 1], fAH[mt], fBL[2], fBL[3]);
                    mma16816(acc[mt][2 * j],     fAL[mt], fBH[0], fBH[1]);
                    mma16816(acc[mt][2 * j + 1], fAL[mt], fBH[2], fBH[3]);
                }
            }
        }
    }

    // store S[c][m][j]
    const int g = l >> 2, t4 = l & 3;
#pragma unroll
    for (int mt = 0; mt < 2; mt++)
#pragma unroll
        for (int nt = 0; nt < 4; nt++) {
            int m = wm * 32 + mt * 16 + g;
            int n = wn * 32 + nt * 8 + t4 * 2;
            size_t o = ((size_t)(c * Mc + m)) * 128 + n;
            *(float2*)&g_spart[o] = make_float2(acc[mt][nt][0], acc[mt][nt][1]);
            *(float2*)&g_spart[o + 8 * 128] = make_float2(acc[mt][nt][2], acc[mt][nt][3]);
        }
}

// ---------------------------------------------------------------------------
// K5: softmax over j + weights.  grid(100), 256 threads (4 lanes per m).
// ---------------------------------------------------------------------------
__global__ void __launch_bounds__(256)
softw_kernel(const float* __restrict__ gamma_p) {
    const int c = blockIdx.x;
    const int t = threadIdx.x;
    const int m = t >> 2;
    const int p = t & 3;
    const float* sp = &g_spart[(size_t)(c * Mc + m) * 128];

    float den = 0.f, num = 0.f;
    for (int jj = 0; jj < 25; jj++) {
        int j = p * 25 + jj;
        float e = expf(sp[j]);
        den += e;
        if (j == c) num = e;
    }
    den += __shfl_xor_sync(0xffffffffu, den, 1);
    den += __shfl_xor_sync(0xffffffffu, den, 2);
    num += __shfl_xor_sync(0xffffffffu, num, 1);
    num += __shfl_xor_sync(0xffffffffu, num, 2);

    if (p == 0) {
        float pcc = num / den;
        float KL  = log2f((1.f + 1e-6f) / (pcc + 1e-6f));
        g_w[c * Mc + m] = expf(KL * gamma_p[0]);
    }
}

// ---------------------------------------------------------------------------
// K6: kwd[c,d] = cnt[c,d] * sum_m keys[c,m,d]*w[c,m]. grid(100,2), 256 thr.
// ---------------------------------------------------------------------------
__global__ void __launch_bounds__(256)
kwd_kernel(const float* __restrict__ keys) {
    __shared__ float ws[Mc];
    const int c = blockIdx.x;
    const int t = threadIdx.x;
    const int d = blockIdx.y * 256 + t;
    if (t < Mc) ws[t] = g_w[c * Mc + t];
    __syncthreads();

    float s = 0.f;
#pragma unroll 8
    for (int m = 0; m < Mc; m++)
        s += keys[((size_t)(c * Mc + m)) * Dc + d] * ws[m];
    g_kwd[c * Dc + d] = s * g_cnt[c * Dc + d];
}

// ---------------------------------------------------------------------------
// K7: final fused epilogue (dense). grid(100), 256 threads.
// ---------------------------------------------------------------------------
__global__ void __launch_bounds__(256)
final_kernel(const float* __restrict__ text, const float* __restrict__ ls_p,
             const float* __restrict__ alpha_p, const float* __restrict__ beta_p,
             float* __restrict__ out) {
    __shared__ float tc[512];
    __shared__ float kd[512];

    const int c = blockIdx.x;
    const int t = threadIdx.x;

    tc[t]       = text[c * Dc + t];
    tc[t + 256] = text[c * Dc + 256 + t];
    kd[t]       = g_kwd[c * Dc + t];
    kd[t + 256] = g_kwd[c * Dc + 256 + t];
    __syncthreads();

    const int b = t >> 2;
    const int p = t & 3;
    const float* fb = &g_f[b * Dc];

    float clip = 0.f, cache = 0.f;
#pragma unroll 8
    for (int q = 0; q < 32; q++) {
        float4 fv = *(const float4*)&fb[p * 128 + q * 4];
        float4 tv = *(const float4*)&tc[p * 128 + q * 4];
        float4 kv = *(const float4*)&kd[p * 128 + q * 4];
        clip  += fv.x * tv.x + fv.y * tv.y + fv.z * tv.z + fv.w * tv.w;
        cache += fv.x * kv.x + fv.y * kv.y + fv.z * kv.z + fv.w * kv.w;
    }
    clip  += __shfl_xor_sync(0xffffffffu, clip, 1);
    clip  += __shfl_xor_sync(0xffffffffu, clip, 2);
    cache += __shfl_xor_sync(0xffffffffu, cache, 1);
    cache += __shfl_xor_sync(0xffffffffu, cache, 2);

    if (p == 0) {
        float cl = cache * (1.f / (float)Mc);
        float cache_logit = expf(beta_p[0] * cl - beta_p[0]);
        out[b * Cc + c] = alpha_p[0] * cache_logit + expf(ls_p[0]) * clip;
    }
}

// ---------------------------------------------------------------------------
// Launch: GEMM first on s0 (starts immediately); tiny tensor-core branch B
// forked onto s2 drains in the GEMM tail alongside rednorm.
// ---------------------------------------------------------------------------
extern "C" void kernel_launch(void* const* d_in, const int* in_sizes, int n_in,
                              void* d_out, int out_size) {
    const float* image   = (const float*)d_in[0];
    const float* W_enc   = (const float*)d_in[1];
    const float* text    = (const float*)d_in[2];
    const float* keys    = (const float*)d_in[3];
    const float* ls      = (const float*)d_in[4];
    const int*   indices = (const int*)d_in[5];
    const float* alpha   = (const float*)d_in[6];
    const float* beta    = (const float*)d_in[7];
    const float* gamma   = (const float*)d_in[8];
    float* out = (float*)d_out;

    static cudaStream_t s2 = nullptr;
    static cudaEvent_t evFork = nullptr, evJoin = nullptr;
    if (s2 == nullptr) {
        cudaStreamCreateWithFlags(&s2, cudaStreamNonBlocking);
        cudaEventCreateWithFlags(&evFork, cudaEventDisableTiming);
        cudaEventCreateWithFlags(&evJoin, cudaEventDisableTiming);
        cudaFuncSetAttribute(gemm_mma_kernel,
                             cudaFuncAttributeMaxDynamicSharedMemorySize, GEMM_SMEM);
        cudaFuncSetAttribute(skey_kernel,
                             cudaFuncAttributeMaxDynamicSharedMemorySize, SKEY_SMEM);
    }

    // fork
    cudaEventRecord(evFork, 0);
    cudaStreamWaitEvent(s2, evFork, 0);

    // branch A (stream 0): GEMM first — starts immediately
    gemm_mma_kernel<<<dim3(2, NCH), 512, GEMM_SMEM>>>(image, W_enc);
    rednorm_kernel<<<Bc, 512>>>();

    // branch B (s2): tensor-core skey + tiny epilogue kernels
    skey_kernel<<<Cc, 256, SKEY_SMEM, s2>>>(keys, text, indices);
    cnt_kernel<<<Cc, 256, 0, s2>>>(indices);
    softw_kernel<<<Cc, 256, 0, s2>>>(gamma);
    kwd_kernel<<<dim3(Cc, 2), 256, 0, s2>>>(keys);

    // join
    cudaEventRecord(evJoin, s2);
    cudaStreamWaitEvent(0, evJoin, 0);

    final_kernel<<<Cc, 256>>>(text, ls, alpha, beta, out);
}

// round 13
// speedup vs baseline: 1.0332x; 1.0332x over previous
#include <cuda_runtime.h>
#include <cuda_bf16.h>

typedef unsigned int u32;
typedef unsigned long long u64;

#define Bc   64
#define DINc 150528
#define Dc   512
#define Cc   100
#define Mc   64
#define NFc  256
#define KC   2048
#define NCH  74          // 73 full chunks of 2048 + last chunk of 1024
#define DT   256

__device__ float g_partial[NCH * Bc * Dc];   // split-K partials [chunk][b][d]
__device__ float g_f[Bc * Dc];
__device__ float g_kwd[Cc * Dc];

// ---------------- helpers ----------------
__device__ __forceinline__ u32 smem_u32(const void* p) {
    u32 a;
    asm("{ .reg .u64 t; cvta.to.shared.u64 t, %1; cvt.u32.u64 %0, t; }" : "=r"(a) : "l"(p));
    return a;
}
__device__ __forceinline__ void cvt_split(float x0, float x1, u32& h, u32& l) {
    asm("cvt.rn.bf16x2.f32 %0, %1, %2;" : "=r"(h) : "f"(x1), "f"(x0));
    float h0 = __int_as_float(h << 16);
    float h1 = __int_as_float(h & 0xFFFF0000u);
    asm("cvt.rn.bf16x2.f32 %0, %1, %2;" : "=r"(l) : "f"(x1 - h1), "f"(x0 - h0));
}
__device__ __forceinline__ void ldmA(u32* r, u32 addr) {
    asm volatile("ldmatrix.sync.aligned.m8n8.x4.shared.b16 {%0,%1,%2,%3}, [%4];"
        : "=r"(r[0]), "=r"(r[1]), "=r"(r[2]), "=r"(r[3]) : "r"(addr));
}
__device__ __forceinline__ void ldmBT(u32* r, u32 addr) {
    asm volatile("ldmatrix.sync.aligned.m8n8.x4.trans.shared.b16 {%0,%1,%2,%3}, [%4];"
        : "=r"(r[0]), "=r"(r[1]), "=r"(r[2]), "=r"(r[3]) : "r"(addr));
}
__device__ __forceinline__ void mma16816(float* c, const u32* a, u32 b0, u32 b1) {
    asm volatile(
        "mma.sync.aligned.m16n8k16.row.col.f32.bf16.bf16.f32 "
        "{%0,%1,%2,%3}, {%4,%5,%6,%7}, {%8,%9}, {%0,%1,%2,%3};"
        : "+f"(c[0]), "+f"(c[1]), "+f"(c[2]), "+f"(c[3])
        : "r"(a[0]), "r"(a[1]), "r"(a[2]), "r"(a[3]), "r"(b0), "r"(b1));
}

// ---------------------------------------------------------------------------
// K1: split-bf16 3-pass HMMA split-K GEMM.  DT=256, 512 threads, KC=2048.
// grid(2, 74) = 148 CTAs = one wave.  88064 B smem.  (Measured ~90us.)
// ---------------------------------------------------------------------------
#define A_STRIDE 20
#define B_STRIDE 132
#define A_BUF (64 * A_STRIDE)
#define B_BUF (32 * B_STRIDE)
#define GEMM_SMEM ((4 * A_BUF + 4 * B_BUF) * 4)   // 88064 B

__global__ void __launch_bounds__(512, 1)
gemm_mma_kernel(const float* __restrict__ A, const float* __restrict__ W) {
    extern __shared__ u32 dsm[];
    u32* AsH = dsm;
    u32* AsL = dsm + 2 * A_BUF;
    u32* BsH = dsm + 4 * A_BUF;
    u32* BsL = dsm + 4 * A_BUF + 2 * B_BUF;

    const int t = threadIdx.x, w = t >> 5, l = t & 31;
    const int wm = w >> 3, wn = w & 7;
    const int dt0 = blockIdx.x * DT;
    const size_t kb = (size_t)blockIdx.y * KC;
    const int kmax = (kb + KC <= DINc) ? KC : (int)(DINc - kb);

    const u32 aRowOff = (u32)(wm * 32 + (l & 7) + ((l >> 3) & 1) * 8) * (A_STRIDE * 4)
                        + ((l & 16) ? 16u : 0u);
    const u32 bOff = (u32)((l & 7) + ((l >> 3) & 1) * 8) * (B_STRIDE * 4)
                     + (u32)(wn * 32 + ((l & 16) ? 8 : 0)) * 2;

    const int am = t >> 3, akq = t & 7;
    const int bk = t >> 6, bdq = t & 63;
    const float* Ap = A + (size_t)am * DINc + kb + akq * 4;
    const float* Wp = W + (size_t)(kb + bk) * Dc + dt0 + bdq * 4;

    float acc[2][4][4];
#pragma unroll
    for (int i = 0; i < 2; i++)
#pragma unroll
        for (int j = 0; j < 4; j++)
#pragma unroll
            for (int q = 0; q < 4; q++) acc[i][j][q] = 0.f;

    float4 pfA;
    float4 pfB[4];
    pfA = *(const float4*)Ap;
#pragma unroll
    for (int i = 0; i < 4; i++) pfB[i] = *(const float4*)(Wp + (size_t)(i * 8) * Dc);

    for (int k0 = 0; k0 < kmax; k0 += 32) {
        const int buf = (k0 >> 5) & 1;
        u32* aH = AsH + buf * A_BUF;
        u32* aL = AsL + buf * A_BUF;
        u32* bH = BsH + buf * B_BUF;
        u32* bL = BsL + buf * B_BUF;

        {
            u32 h0, l0, h1, l1;
            cvt_split(pfA.x, pfA.y, h0, l0);
            cvt_split(pfA.z, pfA.w, h1, l1);
            int woff = am * A_STRIDE + akq * 2;
            *(u64*)&aH[woff] = ((u64)h1 << 32) | h0;
            *(u64*)&aL[woff] = ((u64)l1 << 32) | l0;
        }
#pragma unroll
        for (int i = 0; i < 4; i++) {
            u32 h0, l0, h1, l1;
            cvt_split(pfB[i].x, pfB[i].y, h0, l0);
            cvt_split(pfB[i].z, pfB[i].w, h1, l1);
            int woff = (i * 8 + bk) * B_STRIDE + bdq * 2;
            *(u64*)&bH[woff] = ((u64)h1 << 32) | h0;
            *(u64*)&bL[woff] = ((u64)l1 << 32) | l0;
        }
        if (k0 + 32 < kmax) {
            pfA = *(const float4*)(Ap + k0 + 32);
#pragma unroll
            for (int i = 0; i < 4; i++)
                pfB[i] = *(const float4*)(Wp + (size_t)(i * 8 + k0 + 32) * Dc);
        }
        __syncthreads();

        const u32 aHb = smem_u32(aH), aLb = smem_u32(aL);
        const u32 bHb = smem_u32(bH), bLb = smem_u32(bL);
#pragma unroll
        for (int ks = 0; ks < 2; ks++) {
            u32 fAH[2][4], fAL[2][4];
            ldmA(fAH[0], aHb + aRowOff + ks * 32);
            ldmA(fAH[1], aHb + aRowOff + 16 * (A_STRIDE * 4) + ks * 32);
            ldmA(fAL[0], aLb + aRowOff + ks * 32);
            ldmA(fAL[1], aLb + aRowOff + 16 * (A_STRIDE * 4) + ks * 32);
#pragma unroll
            for (int j = 0; j < 2; j++) {
                u32 fBH[4], fBL[4];
                ldmBT(fBH, bHb + bOff + ks * 16 * (B_STRIDE * 4) + j * 32);
                ldmBT(fBL, bLb + bOff + ks * 16 * (B_STRIDE * 4) + j * 32);
#pragma unroll
                for (int mt = 0; mt < 2; mt++) {
                    mma16816(acc[mt][2 * j],     fAH[mt], fBH[0], fBH[1]);
                    mma16816(acc[mt][2 * j + 1], fAH[mt], fBH[2], fBH[3]);
                    mma16816(acc[mt][2 * j],     fAH[mt], fBL[0], fBL[1]);
                    mma16816(acc[mt][2 * j + 1], fAH[mt], fBL[2], fBL[3]);
                    mma16816(acc[mt][2 * j],     fAL[mt], fBH[0], fBH[1]);
                    mma16816(acc[mt][2 * j + 1], fAL[mt], fBH[2], fBH[3]);
                }
            }
        }
    }

    const int g = l >> 2, t4 = l & 3;
#pragma unroll
    for (int mt = 0; mt < 2; mt++)
#pragma unroll
        for (int nt = 0; nt < 4; nt++) {
            int m = wm * 32 + mt * 16 + g;
            int n = dt0 + wn * 32 + nt * 8 + t4 * 2;
            size_t o = ((size_t)(blockIdx.y * 64 + m)) * Dc + n;
            *(float2*)&g_partial[o] =
                make_float2(acc[mt][nt][0], acc[mt][nt][1]);
            *(float2*)&g_partial[o + 8 * (size_t)Dc] =
                make_float2(acc[mt][nt][2], acc[mt][nt][3]);
        }
}

// ---------------------------------------------------------------------------
// K2: fused reduce split-K + L2-normalize. grid(64), 512 threads.
// ---------------------------------------------------------------------------
__global__ void __launch_bounds__(512)
rednorm_kernel() {
    const int b = blockIdx.x;
    const int t = threadIdx.x;
    float v = 0.f;
#pragma unroll 2
    for (int ch = 0; ch < NCH; ch++)
        v += g_partial[((size_t)ch * Bc + b) * Dc + t];

    float sq = v * v;
    sq += __shfl_xor_sync(0xffffffffu, sq, 1);
    sq += __shfl_xor_sync(0xffffffffu, sq, 2);
    sq += __shfl_xor_sync(0xffffffffu, sq, 4);
    sq += __shfl_xor_sync(0xffffffffu, sq, 8);
    sq += __shfl_xor_sync(0xffffffffu, sq, 16);

    __shared__ float wsum[16];
    __shared__ float inv;
    if ((t & 31) == 0) wsum[t >> 5] = sq;
    __syncthreads();
    if (t < 32) {
        float s = (t < 16) ? wsum[t] : 0.f;
        s += __shfl_xor_sync(0xffffffffu, s, 1);
        s += __shfl_xor_sync(0xffffffffu, s, 2);
        s += __shfl_xor_sync(0xffffffffu, s, 4);
        s += __shfl_xor_sync(0xffffffffu, s, 8);
        if (t == 0) inv = rsqrtf(s);
    }
    __syncthreads();
    g_f[b * Dc + t] = v * inv;
}

// ---------------------------------------------------------------------------
// K3: FUSED key-weight kernel. One CTA per class:
//   1. smem histogram of indices -> cnt[d]
//   2. S[m][j] = sum_k keys[c,m,k] * (cnt[k]*text[j,k])  (split-bf16 HMMA)
//   3. in-smem softmax over j -> w[m] = exp(gamma * KL(p_cc))
//   4. kwd[c,d] = cnt[d] * sum_m keys[c,m,d] * w[m]
// grid(100), 256 threads (8 warps 2x4, warp tile 32x32). Dyn smem 57600 B.
// ---------------------------------------------------------------------------
#define SA_STRIDE 20
#define SB_STRIDE 68
#define SA_BUF (64 * SA_STRIDE)     // 1280 u32
#define SB_BUF (32 * SB_STRIDE)     // 2176 u32
#define HDR 576                      // hist 512 + ws 64
#define SKEY_SMEM ((HDR + 4 * SA_BUF + 4 * SB_BUF) * 4)   // 57600 B

__global__ void __launch_bounds__(256, 1)
skey_fused_kernel(const float* __restrict__ keys, const float* __restrict__ text,
                  const int* __restrict__ indices, const float* __restrict__ gamma_p) {
    extern __shared__ u32 dsm[];
    int*   hist = (int*)dsm;                   // [512]
    float* ws   = (float*)(dsm + 512);         // [64]
    u32* AsH = dsm + HDR;
    u32* AsL = dsm + HDR + 2 * SA_BUF;
    u32* BsH = dsm + HDR + 4 * SA_BUF;
    u32* BsL = dsm + HDR + 4 * SA_BUF + 2 * SB_BUF;
    float* Ssm = (float*)(dsm + HDR + 4 * SA_BUF);   // [64][128], reuses B bufs

    const int c = blockIdx.x;
    const int t = threadIdx.x, w = t >> 5, l = t & 31;
    const int wm = w >> 2, wn = w & 3;

    // 1. per-class index histogram
    hist[t] = 0;
    hist[t + 256] = 0;
    __syncthreads();
    atomicAdd(&hist[indices[c * NFc + t]], 1);
    __syncthreads();

    const u32 aRowOff = (u32)(wm * 32 + (l & 7) + ((l >> 3) & 1) * 8) * (SA_STRIDE * 4)
                        + ((l & 16) ? 16u : 0u);
    const u32 bOff = (u32)((l & 7) + ((l >> 3) & 1) * 8) * (SB_STRIDE * 4)
                     + (u32)(wn * 32 + ((l & 16) ? 8 : 0)) * 2;

    const int am = t >> 3, akq = t & 7;
    const int jj = t & 63, kq0 = t >> 6;
    const int j0 = jj * 2;

    float acc[2][4][4];
#pragma unroll
    for (int i = 0; i < 2; i++)
#pragma unroll
        for (int j = 0; j < 4; j++)
#pragma unroll
            for (int q = 0; q < 4; q++) acc[i][j][q] = 0.f;

    // 2. S via split-bf16 3-pass HMMA over K=512
    for (int k0 = 0; k0 < Dc; k0 += 32) {
        const int buf = (k0 >> 5) & 1;
        u32* aH = AsH + buf * SA_BUF;
        u32* aL = AsL + buf * SA_BUF;
        u32* bH = BsH + buf * SB_BUF;
        u32* bL = BsL + buf * SB_BUF;

#pragma unroll
        for (int i = 0; i < 2; i++) {
            int idx = i * 256 + t;
            int m = idx >> 3, kq = idx & 7;
            float4 v = *(const float4*)&keys[((size_t)(c * Mc + m)) * Dc + k0 + kq * 4];
            u32 h0, l0, h1, l1;
            cvt_split(v.x, v.y, h0, l0);
            cvt_split(v.z, v.w, h1, l1);
            int woff = m * SA_STRIDE + kq * 2;
            *(u64*)&aH[woff] = ((u64)h1 << 32) | h0;
            *(u64*)&aL[woff] = ((u64)l1 << 32) | l0;
        }
#pragma unroll
        for (int it = 0; it < 2; it++) {
            int kq = kq0 + it * 4;
            float4 t0 = make_float4(0.f, 0.f, 0.f, 0.f);
            float4 t1 = make_float4(0.f, 0.f, 0.f, 0.f);
            if (j0 < Cc)     t0 = *(const float4*)&text[(size_t)j0 * Dc + k0 + kq * 4];
            if (j0 + 1 < Cc) t1 = *(const float4*)&text[(size_t)(j0 + 1) * Dc + k0 + kq * 4];
            float cs0 = (float)hist[k0 + kq * 4 + 0];
            float cs1 = (float)hist[k0 + kq * 4 + 1];
            float cs2 = (float)hist[k0 + kq * 4 + 2];
            float cs3 = (float)hist[k0 + kq * 4 + 3];
            float a0[4] = {t0.x * cs0, t0.y * cs1, t0.z * cs2, t0.w * cs3};
            float a1[4] = {t1.x * cs0, t1.y * cs1, t1.z * cs2, t1.w * cs3};
#pragma unroll
            for (int s = 0; s < 4; s++) {
                u32 h, lo;
                cvt_split(a0[s], a1[s], h, lo);
                int woff = (kq * 4 + s) * SB_STRIDE + jj;
                bH[woff] = h;
                bL[woff] = lo;
            }
        }
        __syncthreads();

        const u32 aHb = smem_u32(aH), aLb = smem_u32(aL);
        const u32 bHb = smem_u32(bH), bLb = smem_u32(bL);
#pragma unroll
        for (int ks = 0; ks < 2; ks++) {
            u32 fAH[2][4], fAL[2][4];
            ldmA(fAH[0], aHb + aRowOff + ks * 32);
            ldmA(fAH[1], aHb + aRowOff + 16 * (SA_STRIDE * 4) + ks * 32);
            ldmA(fAL[0], aLb + aRowOff + ks * 32);
            ldmA(fAL[1], aLb + aRowOff + 16 * (SA_STRIDE * 4) + ks * 32);
#pragma unroll
            for (int j = 0; j < 2; j++) {
                u32 fBH[4], fBL[4];
                ldmBT(fBH, bHb + bOff + ks * 16 * (SB_STRIDE * 4) + j * 32);
                ldmBT(fBL, bLb + bOff + ks * 16 * (SB_STRIDE * 4) + j * 32);
#pragma unroll
                for (int mt = 0; mt < 2; mt++) {
                    mma16816(acc[mt][2 * j],     fAH[mt], fBH[0], fBH[1]);
                    mma16816(acc[mt][2 * j + 1], fAH[mt], fBH[2], fBH[3]);
                    mma16816(acc[mt][2 * j],     fAH[mt], fBL[0], fBL[1]);
                    mma16816(acc[mt][2 * j + 1], fAH[mt], fBL[2], fBL[3]);
                    mma16816(acc[mt][2 * j],     fAL[mt], fBH[0], fBH[1]);
                    mma16816(acc[mt][2 * j + 1], fAL[mt], fBH[2], fBH[3]);
                }
            }
        }
        __syncthreads();   // B bufs reused as Ssm after the loop; keep clean edges
    }

    // 3. S fragments -> smem (over B buffers, now dead)
    const int g = l >> 2, t4 = l & 3;
#pragma unroll
    for (int mt = 0; mt < 2; mt++)
#pragma unroll
        for (int nt = 0; nt < 4; nt++) {
            int m = wm * 32 + mt * 16 + g;
            int n = wn * 32 + nt * 8 + t4 * 2;
            *(float2*)&Ssm[m * 128 + n] = make_float2(acc[mt][nt][0], acc[mt][nt][1]);
            *(float2*)&Ssm[(m + 8) * 128 + n] = make_float2(acc[mt][nt][2], acc[mt][nt][3]);
        }
    __syncthreads();

    // softmax over j (4 lanes per m) -> w[m]
    {
        const int m = t >> 2;
        const int p = t & 3;
        const float* sp = &Ssm[m * 128];
        float den = 0.f, num = 0.f;
        for (int q = 0; q < 25; q++) {
            int j = p * 25 + q;
            float e = expf(sp[j]);
            den += e;
            if (j == c) num = e;
        }
        den += __shfl_xor_sync(0xffffffffu, den, 1);
        den += __shfl_xor_sync(0xffffffffu, den, 2);
        num += __shfl_xor_sync(0xffffffffu, num, 1);
        num += __shfl_xor_sync(0xffffffffu, num, 2);
        if (p == 0) {
            float pcc = num / den;
            float KL  = log2f((1.f + 1e-6f) / (pcc + 1e-6f));
            ws[m] = expf(KL * gamma_p[0]);
        }
    }
    __syncthreads();

    // 4. kwd[c,d] = cnt[d] * sum_m keys[c,m,d] * w[m]
#pragma unroll
    for (int i = 0; i < 2; i++) {
        int d = t + i * 256;
        float s = 0.f;
#pragma unroll 8
        for (int m = 0; m < Mc; m++)
            s += keys[((size_t)(c * Mc + m)) * Dc + d] * ws[m];
        g_kwd[c * Dc + d] = s * (float)hist[d];
    }
}

// ---------------------------------------------------------------------------
// K4: final fused epilogue (dense). grid(100), 256 threads.
// ---------------------------------------------------------------------------
__global__ void __launch_bounds__(256)
final_kernel(const float* __restrict__ text, const float* __restrict__ ls_p,
             const float* __restrict__ alpha_p, const float* __restrict__ beta_p,
             float* __restrict__ out) {
    __shared__ float tc[512];
    __shared__ float kd[512];

    const int c = blockIdx.x;
    const int t = threadIdx.x;

    tc[t]       = text[c * Dc + t];
    tc[t + 256] = text[c * Dc + 256 + t];
    kd[t]       = g_kwd[c * Dc + t];
    kd[t + 256] = g_kwd[c * Dc + 256 + t];
    __syncthreads();

    const int b = t >> 2;
    const int p = t & 3;
    const float* fb = &g_f[b * Dc];

    float clip = 0.f, cache = 0.f;
#pragma unroll 8
    for (int q = 0; q < 32; q++) {
        float4 fv = *(const float4*)&fb[p * 128 + q * 4];
        float4 tv = *(const float4*)&tc[p * 128 + q * 4];
        float4 kv = *(const float4*)&kd[p * 128 + q * 4];
        clip  += fv.x * tv.x + fv.y * tv.y + fv.z * tv.z + fv.w * tv.w;
        cache += fv.x * kv.x + fv.y * kv.y + fv.z * kv.z + fv.w * kv.w;
    }
    clip  += __shfl_xor_sync(0xffffffffu, clip, 1);
    clip  += __shfl_xor_sync(0xffffffffu, clip, 2);
    cache += __shfl_xor_sync(0xffffffffu, cache, 1);
    cache += __shfl_xor_sync(0xffffffffu, cache, 2);

    if (p == 0) {
        float cl = cache * (1.f / (float)Mc);
        float cache_logit = expf(beta_p[0] * cl - beta_p[0]);
        out[b * Cc + c] = alpha_p[0] * cache_logit + expf(ls_p[0]) * clip;
    }
}

// ---------------------------------------------------------------------------
// Launch: 4-kernel graph. GEMM first on s0; single fused key kernel forked
// onto s2 (overlaps rednorm / GEMM tail); join; final.
// ---------------------------------------------------------------------------
extern "C" void kernel_launch(void* const* d_in, const int* in_sizes, int n_in,
                              void* d_out, int out_size) {
    const float* image   = (const float*)d_in[0];
    const float* W_enc   = (const float*)d_in[1];
    const float* text    = (const float*)d_in[2];
    const float* keys    = (const float*)d_in[3];
    const float* ls      = (const float*)d_in[4];
    const int*   indices = (const int*)d_in[5];
    const float* alpha   = (const float*)d_in[6];
    const float* beta    = (const float*)d_in[7];
    const float* gamma   = (const float*)d_in[8];
    float* out = (float*)d_out;

    static cudaStream_t s2 = nullptr;
    static cudaEvent_t evFork = nullptr, evJoin = nullptr;
    if (s2 == nullptr) {
        cudaStreamCreateWithFlags(&s2, cudaStreamNonBlocking);
        cudaEventCreateWithFlags(&evFork, cudaEventDisableTiming);
        cudaEventCreateWithFlags(&evJoin, cudaEventDisableTiming);
        cudaFuncSetAttribute(gemm_mma_kernel,
                             cudaFuncAttributeMaxDynamicSharedMemorySize, GEMM_SMEM);
        cudaFuncSetAttribute(skey_fused_kernel,
                             cudaFuncAttributeMaxDynamicSharedMemorySize, SKEY_SMEM);
    }

    // fork
    cudaEventRecord(evFork, 0);
    cudaStreamWaitEvent(s2, evFork, 0);

    // branch A (stream 0)
    gemm_mma_kernel<<<dim3(2, NCH), 512, GEMM_SMEM>>>(image, W_enc);
    rednorm_kernel<<<Bc, 512>>>();

    // branch B (s2): one fused kernel
    skey_fused_kernel<<<Cc, 256, SKEY_SMEM, s2>>>(keys, text, indices, gamma);

    // join
    cudaEventRecord(evJoin, s2);
    cudaStreamWaitEvent(0, evJoin, 0);

    final_kernel<<<Cc, 256>>>(text, ls, alpha, beta, out);
}